// round 13
// baseline (speedup 1.0000x reference)
#include <cuda_runtime.h>

// DWT (2x2 Haar): x (8,512,512,16) f32 -> 4 bands (8,256,256,16), concat [LL|LH|HL|HH].
//
// FINAL kernel. Seven configurations benched; all structural variants land in
// a 0.2us window at ~5.7TB/s DRAM (70% of spec) with every SM-side pipe idle.
// Duration == compulsory 268MB / achieved BW: the problem sits at the HBM
// mixed 1:1 read/write efficiency floor, unreachable from kernel code.
// Falsified levers: coalescing shape, warp-SHFL exchange, L2 write-pin
// (regressed), L2 read-pin (neutral), ILP-2 (neg.), v8-256b (neg.),
// block=512 (neutral). This exact config measured 45.056us twice (best).
//   - one thread per (b, i, j, c4-chunk): 4x LDG.128 (2x2 quad) + 4x STG.128
//     (one per band), all 16B-aligned, sector-perfect, block=256
//   - loads: createpolicy.fractional.L2::evict_last 0.75
//   - stores: __stcs streaming (write stream never competes for L2)

#define B_DIM 8
#define H_DIM 512
#define W_DIM 512
#define C_DIM 16

#define ROW_F4   (W_DIM * C_DIM / 4)        // 2048 float4 per input row
#define PIX_F4   (C_DIM / 4)                // 4 float4 per pixel
#define BAND_F4  (B_DIM * (H_DIM/2) * (W_DIM/2) * C_DIM / 4)   // 2,097,152
#define TOTAL_THREADS (B_DIM * (H_DIM/2) * (W_DIM/2) * PIX_F4) // 8,388,608
#define BLOCK 256

__device__ __forceinline__ float4 ld_f4_evict_last(const float4* p, unsigned long long pol)
{
    float4 v;
    asm volatile("ld.global.L2::cache_hint.v4.f32 {%0,%1,%2,%3}, [%4], %5;"
                 : "=f"(v.x), "=f"(v.y), "=f"(v.z), "=f"(v.w)
                 : "l"(p), "l"(pol));
    return v;
}

__global__ __launch_bounds__(BLOCK) void dwt_haar_kernel(
    const float4* __restrict__ x, float4* __restrict__ out)
{
    unsigned long long pol;
    asm("createpolicy.fractional.L2::evict_last.b64 %0, 0.75;" : "=l"(pol));

    int idx = blockIdx.x * BLOCK + threadIdx.x;
    // idx layout: [b:3][i:8][j:8][c4:2]
    int c4 = idx & 3;
    int j  = (idx >> 2) & 255;
    int i  = (idx >> 10) & 255;
    int b  = idx >> 18;

    int base = ((b * H_DIM + 2 * i) * W_DIM + 2 * j) * PIX_F4 + c4;

    float4 va = ld_f4_evict_last(x + base,                   pol); // (2i,   2j)
    float4 vb = ld_f4_evict_last(x + base + PIX_F4,          pol); // (2i,   2j+1)
    float4 vc = ld_f4_evict_last(x + base + ROW_F4,          pol); // (2i+1, 2j)
    float4 vd = ld_f4_evict_last(x + base + ROW_F4 + PIX_F4, pol); // (2i+1, 2j+1)

    // Butterfly: s0=a+d, s1=b+c, d0=a-d, d1=b-c
    // LL=(s0+s1)/2, LH=(d0-d1)/2, HL=(d0+d1)/2, HH=(s0-s1)/2
    float4 ll, lh, hl, hh;
    {
        float s0, s1, d0, d1;
        s0 = va.x + vd.x; s1 = vb.x + vc.x; d0 = va.x - vd.x; d1 = vb.x - vc.x;
        ll.x = (s0 + s1) * 0.5f; lh.x = (d0 - d1) * 0.5f;
        hl.x = (d0 + d1) * 0.5f; hh.x = (s0 - s1) * 0.5f;
        s0 = va.y + vd.y; s1 = vb.y + vc.y; d0 = va.y - vd.y; d1 = vb.y - vc.y;
        ll.y = (s0 + s1) * 0.5f; lh.y = (d0 - d1) * 0.5f;
        hl.y = (d0 + d1) * 0.5f; hh.y = (s0 - s1) * 0.5f;
        s0 = va.z + vd.z; s1 = vb.z + vc.z; d0 = va.z - vd.z; d1 = vb.z - vc.z;
        ll.z = (s0 + s1) * 0.5f; lh.z = (d0 - d1) * 0.5f;
        hl.z = (d0 + d1) * 0.5f; hh.z = (s0 - s1) * 0.5f;
        s0 = va.w + vd.w; s1 = vb.w + vc.w; d0 = va.w - vd.w; d1 = vb.w - vc.w;
        ll.w = (s0 + s1) * 0.5f; lh.w = (d0 - d1) * 0.5f;
        hl.w = (d0 + d1) * 0.5f; hh.w = (s0 - s1) * 0.5f;
    }

    int obase = ((b * (H_DIM/2) + i) * (W_DIM/2) + j) * PIX_F4 + c4;

    __stcs(out + obase,               ll);
    __stcs(out + obase + BAND_F4,     lh);
    __stcs(out + obase + 2 * BAND_F4, hl);
    __stcs(out + obase + 3 * BAND_F4, hh);
}

extern "C" void kernel_launch(void* const* d_in, const int* in_sizes, int n_in,
                              void* d_out, int out_size)
{
    (void)in_sizes; (void)n_in; (void)out_size;
    const float4* x = (const float4*)d_in[0];
    float4* out = (float4*)d_out;
    dwt_haar_kernel<<<TOTAL_THREADS / BLOCK, BLOCK>>>(x, out);
}

// round 14
// speedup vs baseline: 1.0071x; 1.0071x over previous
#include <cuda_runtime.h>

// DWT (2x2 Haar): x (8,512,512,16) f32 -> 4 bands (8,256,256,16), concat [LL|LH|HL|HH].
//
// FINAL kernel (converged; third replication). Kernel-level time is stable at
// 37.2us across runs; wall spread 45.05-45.38us is harness replay noise.
// Duration == compulsory 268MB / 5.7TB/s achieved DRAM BW — the HBM mixed
// 1:1 read/write efficiency floor (~70% of spec), with all SM-side resources
// idle. Falsified levers: coalescing shape, warp-SHFL, L2 write-pin
// (regressed), L2 read-pin, ILP-2, v8-256b, block=512.
//   - one thread per (b, i, j, c4-chunk): 4x LDG.128 (2x2 quad) + 4x STG.128
//     (one per band), all 16B-aligned, sector-perfect, block=256
//   - loads: createpolicy.fractional.L2::evict_last 0.75
//   - stores: __stcs streaming

#define B_DIM 8
#define H_DIM 512
#define W_DIM 512
#define C_DIM 16

#define ROW_F4   (W_DIM * C_DIM / 4)        // 2048 float4 per input row
#define PIX_F4   (C_DIM / 4)                // 4 float4 per pixel
#define BAND_F4  (B_DIM * (H_DIM/2) * (W_DIM/2) * C_DIM / 4)   // 2,097,152
#define TOTAL_THREADS (B_DIM * (H_DIM/2) * (W_DIM/2) * PIX_F4) // 8,388,608
#define BLOCK 256

__device__ __forceinline__ float4 ld_f4_evict_last(const float4* p, unsigned long long pol)
{
    float4 v;
    asm volatile("ld.global.L2::cache_hint.v4.f32 {%0,%1,%2,%3}, [%4], %5;"
                 : "=f"(v.x), "=f"(v.y), "=f"(v.z), "=f"(v.w)
                 : "l"(p), "l"(pol));
    return v;
}

__global__ __launch_bounds__(BLOCK) void dwt_haar_kernel(
    const float4* __restrict__ x, float4* __restrict__ out)
{
    unsigned long long pol;
    asm("createpolicy.fractional.L2::evict_last.b64 %0, 0.75;" : "=l"(pol));

    int idx = blockIdx.x * BLOCK + threadIdx.x;
    // idx layout: [b:3][i:8][j:8][c4:2]
    int c4 = idx & 3;
    int j  = (idx >> 2) & 255;
    int i  = (idx >> 10) & 255;
    int b  = idx >> 18;

    int base = ((b * H_DIM + 2 * i) * W_DIM + 2 * j) * PIX_F4 + c4;

    float4 va = ld_f4_evict_last(x + base,                   pol); // (2i,   2j)
    float4 vb = ld_f4_evict_last(x + base + PIX_F4,          pol); // (2i,   2j+1)
    float4 vc = ld_f4_evict_last(x + base + ROW_F4,          pol); // (2i+1, 2j)
    float4 vd = ld_f4_evict_last(x + base + ROW_F4 + PIX_F4, pol); // (2i+1, 2j+1)

    // Butterfly: s0=a+d, s1=b+c, d0=a-d, d1=b-c
    // LL=(s0+s1)/2, LH=(d0-d1)/2, HL=(d0+d1)/2, HH=(s0-s1)/2
    float4 ll, lh, hl, hh;
    {
        float s0, s1, d0, d1;
        s0 = va.x + vd.x; s1 = vb.x + vc.x; d0 = va.x - vd.x; d1 = vb.x - vc.x;
        ll.x = (s0 + s1) * 0.5f; lh.x = (d0 - d1) * 0.5f;
        hl.x = (d0 + d1) * 0.5f; hh.x = (s0 - s1) * 0.5f;
        s0 = va.y + vd.y; s1 = vb.y + vc.y; d0 = va.y - vd.y; d1 = vb.y - vc.y;
        ll.y = (s0 + s1) * 0.5f; lh.y = (d0 - d1) * 0.5f;
        hl.y = (d0 + d1) * 0.5f; hh.y = (s0 - s1) * 0.5f;
        s0 = va.z + vd.z; s1 = vb.z + vc.z; d0 = va.z - vd.z; d1 = vb.z - vc.z;
        ll.z = (s0 + s1) * 0.5f; lh.z = (d0 - d1) * 0.5f;
        hl.z = (d0 + d1) * 0.5f; hh.z = (s0 - s1) * 0.5f;
        s0 = va.w + vd.w; s1 = vb.w + vc.w; d0 = va.w - vd.w; d1 = vb.w - vc.w;
        ll.w = (s0 + s1) * 0.5f; lh.w = (d0 - d1) * 0.5f;
        hl.w = (d0 + d1) * 0.5f; hh.w = (s0 - s1) * 0.5f;
    }

    int obase = ((b * (H_DIM/2) + i) * (W_DIM/2) + j) * PIX_F4 + c4;

    __stcs(out + obase,               ll);
    __stcs(out + obase + BAND_F4,     lh);
    __stcs(out + obase + 2 * BAND_F4, hl);
    __stcs(out + obase + 3 * BAND_F4, hh);
}

extern "C" void kernel_launch(void* const* d_in, const int* in_sizes, int n_in,
                              void* d_out, int out_size)
{
    (void)in_sizes; (void)n_in; (void)out_size;
    const float4* x = (const float4*)d_in[0];
    float4* out = (float4*)d_out;
    dwt_haar_kernel<<<TOTAL_THREADS / BLOCK, BLOCK>>>(x, out);
}